// round 16
// baseline (speedup 1.0000x reference)
#include <cuda_runtime.h>
#include <cuda_fp16.h>
#include <cstdint>

// ---------------- problem constants ----------------
#define TOK   16384
#define DIMD  1024
#define FF    4096
#define NEXP  8
#define TM    128
#define TN    128
#define KT    64
#define ROW_TILES 264
#define R_CAP (ROW_TILES*TM)     // 33792

// gemm CTA: 128 threads, 4 warps (2x2), warp tile 64x64
#define GTHREADS 128

// smem (uint32 words): 3 stages of A(4608) + B(4608); 2 CTAs/SM
// tile row: 64 fp16 = 32 words, padded to stride 36 (conflict-free frags)
#define STAGE_W 4608             // 128 * 36
#define NSTAGE  3
#define SMEM_WORDS (NSTAGE*2*STAGE_W)
#define SMEM_BYTES (SMEM_WORDS*4)   // 110592 B per CTA -> 2 CTAs = 221184 < 228KB

// ---------------- device scratch ----------------
__device__ __half g_xg[(size_t)R_CAP * DIMD];           // gathered x, fp16
__device__ __half g_h[(size_t)R_CAP * FF];              // hidden, fp16
__device__ float  g_y[(size_t)R_CAP * DIMD];            // gemm2 raw output
__device__ __half g_w1t[(size_t)NEXP * FF * DIMD];      // W1^T fp16 [e][f][d]
__device__ __half g_w2t[(size_t)NEXP * DIMD * FF];      // W2^T fp16 [e][d][f]

__device__ int   g_row_token[R_CAP];
__device__ int   g_tok_e[TOK * 2];
__device__ float g_tok_g[TOK * 2];
__device__ int   g_tok_row[TOK * 2];
__device__ int   g_counts[NEXP];
__device__ int   g_off[NEXP + 1];
__device__ int   g_cursor[NEXP];

// ---------------- helpers ----------------
__device__ __forceinline__ uint32_t smem_u32(const void* p) {
    uint32_t a;
    asm("{ .reg .u64 t; cvta.to.shared.u64 t, %1; cvt.u32.u64 %0, t; }" : "=r"(a) : "l"(p));
    return a;
}
__device__ __forceinline__ void cp_async16(uint32_t dst, const void* src) {
    asm volatile("cp.async.cg.shared.global [%0], [%1], 16;" :: "r"(dst), "l"(src));
}
#define CP_COMMIT() asm volatile("cp.async.commit_group;" ::: "memory")
#define CP_WAIT1()  asm volatile("cp.async.wait_group 1;" ::: "memory")
#define CP_WAIT0()  asm volatile("cp.async.wait_group 0;" ::: "memory")

__device__ __forceinline__ void mma_f16(float* d,
    uint32_t a0, uint32_t a1, uint32_t a2, uint32_t a3,
    uint32_t b0, uint32_t b1) {
    asm volatile("mma.sync.aligned.m16n8k16.row.col.f32.f16.f16.f32 "
        "{%0,%1,%2,%3}, {%4,%5,%6,%7}, {%8,%9}, {%0,%1,%2,%3};"
        : "+f"(d[0]), "+f"(d[1]), "+f"(d[2]), "+f"(d[3])
        : "r"(a0), "r"(a1), "r"(a2), "r"(a3), "r"(b0), "r"(b1));
}

// ---------------- routing kernels ----------------
__global__ void init_kernel() {
    int i = blockIdx.x * 256 + threadIdx.x;
    if (i < NEXP) g_counts[i] = 0;
    if (i < R_CAP) g_row_token[i] = 0;
}

__global__ __launch_bounds__(256) void router_kernel(const float* __restrict__ x,
                                                     const float* __restrict__ Wg) {
    __shared__ float sWg[NEXP * DIMD];
    int tid = threadIdx.x;
    for (int i = tid; i < NEXP * DIMD; i += 256) {
        int d = i & (DIMD - 1);
        int e = i >> 10;
        sWg[i] = Wg[d * NEXP + e];
    }
    __syncthreads();
    int warp = tid >> 5, lane = tid & 31;
    int token = blockIdx.x * 8 + warp;
    const float* xr = x + (size_t)token * DIMD;
    float acc[NEXP];
#pragma unroll
    for (int e = 0; e < NEXP; e++) acc[e] = 0.f;
    for (int d = lane; d < DIMD; d += 32) {
        float xv = xr[d];
#pragma unroll
        for (int e = 0; e < NEXP; e++) acc[e] = fmaf(xv, sWg[e * DIMD + d], acc[e]);
    }
#pragma unroll
    for (int e = 0; e < NEXP; e++)
#pragma unroll
        for (int o = 16; o; o >>= 1) acc[e] += __shfl_xor_sync(0xFFFFFFFFu, acc[e], o);
    if (lane == 0) {
        int e0 = 0; float l0 = acc[0];
#pragma unroll
        for (int e = 1; e < NEXP; e++) if (acc[e] > l0) { l0 = acc[e]; e0 = e; }
        int e1 = -1; float l1 = -3.4e38f;
#pragma unroll
        for (int e = 0; e < NEXP; e++) if (e != e0 && acc[e] > l1) { l1 = acc[e]; e1 = e; }
        float g0 = 1.f / (1.f + expf(l1 - l0));
        g_tok_e[token * 2 + 0] = e0;
        g_tok_e[token * 2 + 1] = e1;
        g_tok_g[token * 2 + 0] = g0;
        g_tok_g[token * 2 + 1] = 1.f - g0;
        atomicAdd(&g_counts[e0], 1);
        atomicAdd(&g_counts[e1], 1);
    }
}

__global__ void scan_kernel() {
    if (threadIdx.x == 0) {
        int off = 0;
        for (int e = 0; e < NEXP; e++) {
            g_off[e] = off;
            g_cursor[e] = off;
            off += ((g_counts[e] + TM - 1) / TM) * TM;
        }
        g_off[NEXP] = off;
    }
}

__global__ void assign_kernel() {
    int t = blockIdx.x * 256 + threadIdx.x;
    if (t >= TOK) return;
#pragma unroll
    for (int k = 0; k < 2; k++) {
        int e = g_tok_e[t * 2 + k];
        int p = atomicAdd(&g_cursor[e], 1);
        g_row_token[p] = t;
        g_tok_row[t * 2 + k] = p;
    }
}

// gather x rows to fp16
__global__ __launch_bounds__(256) void prep_x_kernel(const float* __restrict__ x) {
    size_t base = ((size_t)blockIdx.x * 256 + threadIdx.x) * 4;
    int row = (int)(base >> 10);
    int col = (int)(base & 1023);
    int tok = g_row_token[row];
    float4 v = *(const float4*)(x + (size_t)tok * DIMD + col);
    __half2 h0 = __floats2half2_rn(v.x, v.y);
    __half2 h1 = __floats2half2_rn(v.z, v.w);
    *(__half2*)(g_xg + base) = h0;
    *(__half2*)(g_xg + base + 2) = h1;
}

// W1 [e][d][f] fp32 -> g_w1t [e][f][d] fp16
__global__ __launch_bounds__(256) void transpose_w1_kernel(const float* __restrict__ W1) {
    __shared__ float t[32][33];
    int e = blockIdx.z, f0 = blockIdx.x * 32, d0 = blockIdx.y * 32;
    int tx = threadIdx.x, ty = threadIdx.y;
#pragma unroll
    for (int i = 0; i < 32; i += 8)
        t[ty + i][tx] = W1[((size_t)e * DIMD + d0 + ty + i) * FF + f0 + tx];
    __syncthreads();
#pragma unroll
    for (int i = 0; i < 32; i += 8)
        g_w1t[((size_t)e * FF + f0 + ty + i) * DIMD + d0 + tx] = __float2half_rn(t[tx][ty + i]);
}

// W2 [e][f][d] fp32 -> g_w2t [e][d][f] fp16
__global__ __launch_bounds__(256) void transpose_w2_kernel(const float* __restrict__ W2) {
    __shared__ float t[32][33];
    int e = blockIdx.z, d0 = blockIdx.x * 32, f0 = blockIdx.y * 32;
    int tx = threadIdx.x, ty = threadIdx.y;
#pragma unroll
    for (int i = 0; i < 32; i += 8)
        t[ty + i][tx] = W2[((size_t)e * FF + f0 + ty + i) * DIMD + d0 + tx];
    __syncthreads();
#pragma unroll
    for (int i = 0; i < 32; i += 8)
        g_w2t[((size_t)e * DIMD + d0 + ty + i) * FF + f0 + tx] = __float2half_rn(t[tx][ty + i]);
}

// ---------------- fp16 mma mainloop (TM=128, TN=128, KT=64, 4 warps 2x2, warp tile 64x64) ----------------
// smem word layout: row r at stride 36 words; word w = fp16 pair (2w, 2w+1)
struct Frag { float acc[4][8][4]; };

__device__ __forceinline__ void load_tile(uint32_t* As, uint32_t* Bs, int s, int kt,
                                          const __half* Agm, int lda,
                                          const __half* Bgm, int ldb, int tid) {
#pragma unroll
    for (int i = 0; i < 8; i++) {           // A: 128 rows x 8 chunks = 1024
        int c = tid + i * GTHREADS;
        int r = c >> 3, ch = c & 7;
        uint32_t dst = smem_u32(&As[s * STAGE_W + r * 36 + ch * 4]);
        cp_async16(dst, Agm + (size_t)r * lda + kt * KT + ch * 8);
    }
#pragma unroll
    for (int i = 0; i < 8; i++) {           // B: 128 n-rows x 8 chunks = 1024
        int c = tid + i * GTHREADS;
        int r = c >> 3, ch = c & 7;
        uint32_t dst = smem_u32(&Bs[s * STAGE_W + r * 36 + ch * 4]);
        cp_async16(dst, Bgm + (size_t)r * ldb + kt * KT + ch * 8);
    }
}

__device__ __forceinline__ void gemm_mainloop(Frag& F, uint32_t* As, uint32_t* Bs,
                                              const __half* Agm, int lda,
                                              const __half* Bgm, int ldb,
                                              int ktiles, int tid) {
    int lane = tid & 31, wid = tid >> 5;
    int warp_m = wid & 1, warp_n = wid >> 1;   // 2x2 warps
    int gid = lane >> 2, tig = lane & 3;

    int arow[4], brow[8];
#pragma unroll
    for (int mt = 0; mt < 4; mt++) arow[mt] = (warp_m * 64 + mt * 16 + gid) * 36 + tig;
#pragma unroll
    for (int nt = 0; nt < 8; nt++) brow[nt] = (warp_n * 64 + nt * 8 + gid) * 36 + tig;

#pragma unroll
    for (int mt = 0; mt < 4; mt++)
#pragma unroll
        for (int nt = 0; nt < 8; nt++)
#pragma unroll
            for (int q = 0; q < 4; q++) F.acc[mt][nt][q] = 0.f;

    load_tile(As, Bs, 0, 0, Agm, lda, Bgm, ldb, tid); CP_COMMIT();
    load_tile(As, Bs, 1, 1, Agm, lda, Bgm, ldb, tid); CP_COMMIT();

    for (int kt = 0; kt < ktiles; kt++) {
        int s = kt % 3;
        CP_WAIT1();
        __syncthreads();
        int ktn = kt + 2;
        if (ktn < ktiles)
            load_tile(As, Bs, ktn % 3, ktn, Agm, lda, Bgm, ldb, tid);
        CP_COMMIT();

        const uint32_t* as = As + s * STAGE_W;
        const uint32_t* bs = Bs + s * STAGE_W;
#pragma unroll
        for (int ks = 0; ks < 4; ks++) {        // KT=64 -> four k16 steps
            int ko = ks * 8;
            uint32_t af[4][4];
#pragma unroll
            for (int mt = 0; mt < 4; mt++) {
                af[mt][0] = as[arow[mt] + ko];              // (r,    k)
                af[mt][1] = as[arow[mt] + 288 + ko];        // (r+8,  k)  288 = 8*36
                af[mt][2] = as[arow[mt] + ko + 4];          // (r,    k+8)
                af[mt][3] = as[arow[mt] + 288 + ko + 4];    // (r+8,  k+8)
            }
            uint32_t bf[8][2];
#pragma unroll
            for (int nt = 0; nt < 8; nt++) {
                bf[nt][0] = bs[brow[nt] + ko];              // (k,    n)
                bf[nt][1] = bs[brow[nt] + ko + 4];          // (k+8,  n)
            }
#pragma unroll
            for (int mt = 0; mt < 4; mt++)
#pragma unroll
                for (int nt = 0; nt < 8; nt++)
                    mma_f16(F.acc[mt][nt], af[mt][0], af[mt][1], af[mt][2], af[mt][3],
                            bf[nt][0], bf[nt][1]);
        }
    }
    CP_WAIT0();
}

// ---------------- GEMM1: h = fp16(relu(g_xg @ W1t^T + b1[e])) ----------------
// bid.x = row*2 + n_lo (row-fastest, N-pairs co-resident), bid.y = n_hi
__global__ __launch_bounds__(GTHREADS, 2) void gemm1_kernel(const float* __restrict__ b1) {
    extern __shared__ uint32_t sm[];
    uint32_t* As = sm;
    uint32_t* Bs = sm + NSTAGE * STAGE_W;
    int tid = threadIdx.x;
    int row0 = (blockIdx.x >> 1) * TM;
    if (row0 >= g_off[NEXP]) return;
    int n0 = (blockIdx.y * 2 + (blockIdx.x & 1)) * TN;
    int e = 0;
#pragma unroll
    for (int i = 1; i < NEXP; i++) e += (row0 >= g_off[i]) ? 1 : 0;

    const __half* Agm = g_xg + (size_t)row0 * DIMD;
    const __half* Bgm = g_w1t + (size_t)e * FF * DIMD + (size_t)n0 * DIMD;

    Frag F;
    gemm_mainloop(F, As, Bs, Agm, DIMD, Bgm, DIMD, DIMD / KT, tid);

    int lane = tid & 31, wid = tid >> 5;
    int warp_m = wid & 1, warp_n = wid >> 1;
    int gid = lane >> 2, tig = lane & 3;
    const float* bias = b1 + e * FF + n0;

#pragma unroll
    for (int nt = 0; nt < 8; nt++) {
        int gc = warp_n * 64 + nt * 8 + tig * 2;
        float bv0 = __ldg(bias + gc), bv1 = __ldg(bias + gc + 1);
#pragma unroll
        for (int mt = 0; mt < 4; mt++) {
            int gr0 = row0 + warp_m * 64 + mt * 16 + gid;
            __half2 v0 = __floats2half2_rn(fmaxf(F.acc[mt][nt][0] + bv0, 0.f),
                                           fmaxf(F.acc[mt][nt][1] + bv1, 0.f));
            __half2 v1 = __floats2half2_rn(fmaxf(F.acc[mt][nt][2] + bv0, 0.f),
                                           fmaxf(F.acc[mt][nt][3] + bv1, 0.f));
            *(__half2*)(g_h + (size_t)gr0 * FF + n0 + gc) = v0;
            *(__half2*)(g_h + (size_t)(gr0 + 8) * FF + n0 + gc) = v1;
        }
    }
}

// ---------------- GEMM2: y = h @ W2t^T  (bias+gate applied in combine) ----------------
__global__ __launch_bounds__(GTHREADS, 2) void gemm2_kernel() {
    extern __shared__ uint32_t sm[];
    uint32_t* As = sm;
    uint32_t* Bs = sm + NSTAGE * STAGE_W;
    int tid = threadIdx.x;
    int row0 = (blockIdx.x >> 1) * TM;
    if (row0 >= g_off[NEXP]) return;
    int n0 = (blockIdx.y * 2 + (blockIdx.x & 1)) * TN;
    int e = 0;
#pragma unroll
    for (int i = 1; i < NEXP; i++) e += (row0 >= g_off[i]) ? 1 : 0;

    const __half* Agm = g_h + (size_t)row0 * FF;
    const __half* Bgm = g_w2t + (size_t)e * DIMD * FF + (size_t)n0 * FF;

    Frag F;
    gemm_mainloop(F, As, Bs, Agm, FF, Bgm, FF, FF / KT, tid);

    int lane = tid & 31, wid = tid >> 5;
    int warp_m = wid & 1, warp_n = wid >> 1;
    int gid = lane >> 2, tig = lane & 3;

#pragma unroll
    for (int nt = 0; nt < 8; nt++) {
        int gc = warp_n * 64 + nt * 8 + tig * 2;
#pragma unroll
        for (int mt = 0; mt < 4; mt++) {
            int gr0 = row0 + warp_m * 64 + mt * 16 + gid;
            float2 v0 = { F.acc[mt][nt][0], F.acc[mt][nt][1] };
            float2 v1 = { F.acc[mt][nt][2], F.acc[mt][nt][3] };
            *(float2*)(g_y + (size_t)gr0 * DIMD + n0 + gc) = v0;
            *(float2*)(g_y + (size_t)(gr0 + 8) * DIMD + n0 + gc) = v1;
        }
    }
}

// ---------------- combine: out[t] = sum_k g_k*(y[row_k] + b2[e_k]) ----------------
__global__ __launch_bounds__(256) void combine_kernel(const float* __restrict__ b2,
                                                      float* __restrict__ out) {
    int t = blockIdx.x;
    int d = threadIdx.x * 4;
    int r0 = g_tok_row[t * 2], r1 = g_tok_row[t * 2 + 1];
    int e0 = g_tok_e[t * 2],   e1 = g_tok_e[t * 2 + 1];
    float gg0 = g_tok_g[t * 2], gg1 = g_tok_g[t * 2 + 1];
    float4 y0 = *(const float4*)(g_y + (size_t)r0 * DIMD + d);
    float4 y1 = *(const float4*)(g_y + (size_t)r1 * DIMD + d);
    float4 bA = *(const float4*)(b2 + (size_t)e0 * DIMD + d);
    float4 bB = *(const float4*)(b2 + (size_t)e1 * DIMD + d);
    float4 o;
    o.x = gg0 * (y0.x + bA.x) + gg1 * (y1.x + bB.x);
    o.y = gg0 * (y0.y + bA.y) + gg1 * (y1.y + bB.y);
    o.z = gg0 * (y0.z + bA.z) + gg1 * (y1.z + bB.z);
    o.w = gg0 * (y0.w + bA.w) + gg1 * (y1.w + bB.w);
    *(float4*)(out + (size_t)t * DIMD + d) = o;
}

// ---------------- host launch ----------------
extern "C" void kernel_launch(void* const* d_in, const int* in_sizes, int n_in,
                              void* d_out, int out_size) {
    const float* x  = (const float*)d_in[0];
    const float* Wg = (const float*)d_in[1];
    const float* W1 = (const float*)d_in[2];
    const float* b1 = (const float*)d_in[3];
    const float* W2 = (const float*)d_in[4];
    const float* b2 = (const float*)d_in[5];
    float* out = (float*)d_out;

    cudaFuncSetAttribute(gemm1_kernel, cudaFuncAttributeMaxDynamicSharedMemorySize, SMEM_BYTES);
    cudaFuncSetAttribute(gemm2_kernel, cudaFuncAttributeMaxDynamicSharedMemorySize, SMEM_BYTES);

    init_kernel<<<R_CAP / 256, 256>>>();
    router_kernel<<<TOK / 8, 256>>>(x, Wg);
    scan_kernel<<<1, 32>>>();
    assign_kernel<<<TOK / 256, 256>>>();
    prep_x_kernel<<<(R_CAP * (DIMD / 4)) / 256, 256>>>(x);
    transpose_w1_kernel<<<dim3(FF / 32, DIMD / 32, NEXP), dim3(32, 8)>>>(W1);
    transpose_w2_kernel<<<dim3(DIMD / 32, FF / 32, NEXP), dim3(32, 8)>>>(W2);
    gemm1_kernel<<<dim3(ROW_TILES * 2, FF / (TN * 2)), GTHREADS, SMEM_BYTES>>>(b1);
    gemm2_kernel<<<dim3(ROW_TILES * 2, DIMD / (TN * 2)), GTHREADS, SMEM_BYTES>>>();
    combine_kernel<<<TOK, 256>>>(b2, out);
}

// round 17
// speedup vs baseline: 1.0093x; 1.0093x over previous
#include <cuda_runtime.h>
#include <cuda_fp16.h>
#include <cstdint>

// ---------------- problem constants ----------------
#define TOK   16384
#define DIMD  1024
#define FF    4096
#define NEXP  8
#define TM    128
#define TN    128
#define KT    64
#define ROW_TILES 264
#define R_CAP (ROW_TILES*TM)     // 33792

// smem (uint32 words): 3 stages of A(4608) + B(4608); 2 CTAs/SM
// tile row: 64 fp16 = 32 words, padded to stride 36 (conflict-free frags)
#define STAGE_W 4608             // 128 * 36
#define NSTAGE  3
#define SMEM_WORDS (NSTAGE*2*STAGE_W)
#define SMEM_BYTES (SMEM_WORDS*4)   // 110592 B per CTA -> 2 CTAs = 221184 < 228KB

// ---------------- device scratch ----------------
__device__ __half g_xg[(size_t)R_CAP * DIMD];           // gathered x, fp16
__device__ __half g_h[(size_t)R_CAP * FF];              // hidden, fp16
__device__ float  g_y[(size_t)R_CAP * DIMD];            // gemm2 raw output
__device__ __half g_w1t[(size_t)NEXP * FF * DIMD];      // W1^T fp16 [e][f][d]
__device__ __half g_w2t[(size_t)NEXP * DIMD * FF];      // W2^T fp16 [e][d][f]

__device__ int   g_row_token[R_CAP];
__device__ int   g_tok_e[TOK * 2];
__device__ float g_tok_g[TOK * 2];
__device__ int   g_tok_row[TOK * 2];
__device__ int   g_counts[NEXP];
__device__ int   g_off[NEXP + 1];
__device__ int   g_cursor[NEXP];

// ---------------- helpers ----------------
__device__ __forceinline__ uint32_t smem_u32(const void* p) {
    uint32_t a;
    asm("{ .reg .u64 t; cvta.to.shared.u64 t, %1; cvt.u32.u64 %0, t; }" : "=r"(a) : "l"(p));
    return a;
}
__device__ __forceinline__ void cp_async16(uint32_t dst, const void* src) {
    asm volatile("cp.async.cg.shared.global [%0], [%1], 16;" :: "r"(dst), "l"(src));
}
#define CP_COMMIT() asm volatile("cp.async.commit_group;" ::: "memory")
#define CP_WAIT1()  asm volatile("cp.async.wait_group 1;" ::: "memory")
#define CP_WAIT0()  asm volatile("cp.async.wait_group 0;" ::: "memory")

__device__ __forceinline__ void mma_f16(float* d,
    uint32_t a0, uint32_t a1, uint32_t a2, uint32_t a3,
    uint32_t b0, uint32_t b1) {
    asm volatile("mma.sync.aligned.m16n8k16.row.col.f32.f16.f16.f32 "
        "{%0,%1,%2,%3}, {%4,%5,%6,%7}, {%8,%9}, {%0,%1,%2,%3};"
        : "+f"(d[0]), "+f"(d[1]), "+f"(d[2]), "+f"(d[3])
        : "r"(a0), "r"(a1), "r"(a2), "r"(a3), "r"(b0), "r"(b1));
}

// ---------------- routing kernels ----------------
__global__ void init_kernel() {
    int i = blockIdx.x * 256 + threadIdx.x;
    if (i < NEXP) g_counts[i] = 0;
    if (i < R_CAP) g_row_token[i] = 0;
}

__global__ __launch_bounds__(256) void router_kernel(const float* __restrict__ x,
                                                     const float* __restrict__ Wg) {
    __shared__ float sWg[NEXP * DIMD];
    int tid = threadIdx.x;
    for (int i = tid; i < NEXP * DIMD; i += 256) {
        int d = i & (DIMD - 1);
        int e = i >> 10;
        sWg[i] = Wg[d * NEXP + e];
    }
    __syncthreads();
    int warp = tid >> 5, lane = tid & 31;
    int token = blockIdx.x * 8 + warp;
    const float* xr = x + (size_t)token * DIMD;
    float acc[NEXP];
#pragma unroll
    for (int e = 0; e < NEXP; e++) acc[e] = 0.f;
    for (int d = lane; d < DIMD; d += 32) {
        float xv = xr[d];
#pragma unroll
        for (int e = 0; e < NEXP; e++) acc[e] = fmaf(xv, sWg[e * DIMD + d], acc[e]);
    }
#pragma unroll
    for (int e = 0; e < NEXP; e++)
#pragma unroll
        for (int o = 16; o; o >>= 1) acc[e] += __shfl_xor_sync(0xFFFFFFFFu, acc[e], o);
    if (lane == 0) {
        int e0 = 0; float l0 = acc[0];
#pragma unroll
        for (int e = 1; e < NEXP; e++) if (acc[e] > l0) { l0 = acc[e]; e0 = e; }
        int e1 = -1; float l1 = -3.4e38f;
#pragma unroll
        for (int e = 0; e < NEXP; e++) if (e != e0 && acc[e] > l1) { l1 = acc[e]; e1 = e; }
        float g0 = 1.f / (1.f + expf(l1 - l0));
        g_tok_e[token * 2 + 0] = e0;
        g_tok_e[token * 2 + 1] = e1;
        g_tok_g[token * 2 + 0] = g0;
        g_tok_g[token * 2 + 1] = 1.f - g0;
        atomicAdd(&g_counts[e0], 1);
        atomicAdd(&g_counts[e1], 1);
    }
}

__global__ void scan_kernel() {
    if (threadIdx.x == 0) {
        int off = 0;
        for (int e = 0; e < NEXP; e++) {
            g_off[e] = off;
            g_cursor[e] = off;
            off += ((g_counts[e] + TM - 1) / TM) * TM;
        }
        g_off[NEXP] = off;
    }
}

__global__ void assign_kernel() {
    int t = blockIdx.x * 256 + threadIdx.x;
    if (t >= TOK) return;
#pragma unroll
    for (int k = 0; k < 2; k++) {
        int e = g_tok_e[t * 2 + k];
        int p = atomicAdd(&g_cursor[e], 1);
        g_row_token[p] = t;
        g_tok_row[t * 2 + k] = p;
    }
}

// gather x rows to fp16
__global__ __launch_bounds__(256) void prep_x_kernel(const float* __restrict__ x) {
    size_t base = ((size_t)blockIdx.x * 256 + threadIdx.x) * 4;
    int row = (int)(base >> 10);
    int col = (int)(base & 1023);
    int tok = g_row_token[row];
    float4 v = *(const float4*)(x + (size_t)tok * DIMD + col);
    __half2 h0 = __floats2half2_rn(v.x, v.y);
    __half2 h1 = __floats2half2_rn(v.z, v.w);
    *(__half2*)(g_xg + base) = h0;
    *(__half2*)(g_xg + base + 2) = h1;
}

// W1 [e][d][f] fp32 -> g_w1t [e][f][d] fp16  (64x64 tile, half2 full-rate stores)
__global__ __launch_bounds__(256) void transpose_w1_kernel(const float* __restrict__ W1) {
    __shared__ float t[64][65];
    int e = blockIdx.z, f0 = blockIdx.x * 64, d0 = blockIdx.y * 64;
    int tx = threadIdx.x, ty = threadIdx.y;   // 32 x 8
#pragma unroll
    for (int i = 0; i < 64; i += 8) {
        const float* src = W1 + ((size_t)e * DIMD + d0 + ty + i) * FF + f0;
        t[ty + i][tx]      = src[tx];
        t[ty + i][tx + 32] = src[tx + 32];
    }
    __syncthreads();
#pragma unroll
    for (int i = 0; i < 64; i += 8) {
        int f = f0 + ty + i;
        __half2 v = __floats2half2_rn(t[tx * 2][ty + i], t[tx * 2 + 1][ty + i]);
        *(__half2*)&g_w1t[((size_t)e * FF + f) * DIMD + d0 + tx * 2] = v;
    }
}

// W2 [e][f][d] fp32 -> g_w2t [e][d][f] fp16  (64x64 tile, half2 full-rate stores)
__global__ __launch_bounds__(256) void transpose_w2_kernel(const float* __restrict__ W2) {
    __shared__ float t[64][65];
    int e = blockIdx.z, d0 = blockIdx.x * 64, f0 = blockIdx.y * 64;
    int tx = threadIdx.x, ty = threadIdx.y;
#pragma unroll
    for (int i = 0; i < 64; i += 8) {
        const float* src = W2 + ((size_t)e * FF + f0 + ty + i) * DIMD + d0;
        t[ty + i][tx]      = src[tx];
        t[ty + i][tx + 32] = src[tx + 32];
    }
    __syncthreads();
#pragma unroll
    for (int i = 0; i < 64; i += 8) {
        int d = d0 + ty + i;
        __half2 v = __floats2half2_rn(t[tx * 2][ty + i], t[tx * 2 + 1][ty + i]);
        *(__half2*)&g_w2t[((size_t)e * DIMD + d) * FF + f0 + tx * 2] = v;
    }
}

// ---------------- fp16 mma mainloop (TM=128, TN=128, KT=64, 8 warps 2x4) ----------------
// smem word layout: row r at stride 36 words; word w = fp16 pair (2w, 2w+1)
struct Frag { float acc[4][4][4]; };

__device__ __forceinline__ void load_tile(uint32_t* As, uint32_t* Bs, int s, int kt,
                                          const __half* Agm, int lda,
                                          const __half* Bgm, int ldb, int tid) {
#pragma unroll
    for (int i = 0; i < 4; i++) {           // A: 128 rows x 8 chunks = 1024
        int c = tid + i * 256;
        int r = c >> 3, ch = c & 7;
        uint32_t dst = smem_u32(&As[s * STAGE_W + r * 36 + ch * 4]);
        cp_async16(dst, Agm + (size_t)r * lda + kt * KT + ch * 8);
    }
#pragma unroll
    for (int i = 0; i < 4; i++) {           // B: 128 n-rows x 8 chunks = 1024
        int c = tid + i * 256;
        int r = c >> 3, ch = c & 7;
        uint32_t dst = smem_u32(&Bs[s * STAGE_W + r * 36 + ch * 4]);
        cp_async16(dst, Bgm + (size_t)r * ldb + kt * KT + ch * 8);
    }
}

__device__ __forceinline__ void gemm_mainloop(Frag& F, uint32_t* As, uint32_t* Bs,
                                              const __half* Agm, int lda,
                                              const __half* Bgm, int ldb,
                                              int ktiles, int tid) {
    int lane = tid & 31, wid = tid >> 5;
    int warp_m = wid & 1, warp_n = wid >> 1;
    int gid = lane >> 2, tig = lane & 3;

    int arow[4], brow[4];
#pragma unroll
    for (int mt = 0; mt < 4; mt++) arow[mt] = (warp_m * 64 + mt * 16 + gid) * 36 + tig;
#pragma unroll
    for (int nt = 0; nt < 4; nt++) brow[nt] = (warp_n * 32 + nt * 8 + gid) * 36 + tig;

#pragma unroll
    for (int mt = 0; mt < 4; mt++)
#pragma unroll
        for (int nt = 0; nt < 4; nt++)
#pragma unroll
            for (int q = 0; q < 4; q++) F.acc[mt][nt][q] = 0.f;

    load_tile(As, Bs, 0, 0, Agm, lda, Bgm, ldb, tid); CP_COMMIT();
    load_tile(As, Bs, 1, 1, Agm, lda, Bgm, ldb, tid); CP_COMMIT();

    for (int kt = 0; kt < ktiles; kt++) {
        int s = kt % 3;
        CP_WAIT1();
        __syncthreads();
        int ktn = kt + 2;
        if (ktn < ktiles)
            load_tile(As, Bs, ktn % 3, ktn, Agm, lda, Bgm, ldb, tid);
        CP_COMMIT();

        const uint32_t* as = As + s * STAGE_W;
        const uint32_t* bs = Bs + s * STAGE_W;
#pragma unroll
        for (int ks = 0; ks < 4; ks++) {        // KT=64 -> four k16 steps
            int ko = ks * 8;
            uint32_t af[4][4];
#pragma unroll
            for (int mt = 0; mt < 4; mt++) {
                af[mt][0] = as[arow[mt] + ko];              // (r,    k)
                af[mt][1] = as[arow[mt] + 288 + ko];        // (r+8,  k)  288 = 8*36
                af[mt][2] = as[arow[mt] + ko + 4];          // (r,    k+8)
                af[mt][3] = as[arow[mt] + 288 + ko + 4];    // (r+8,  k+8)
            }
            uint32_t bf[4][2];
#pragma unroll
            for (int nt = 0; nt < 4; nt++) {
                bf[nt][0] = bs[brow[nt] + ko];              // (k,    n)
                bf[nt][1] = bs[brow[nt] + ko + 4];          // (k+8,  n)
            }
#pragma unroll
            for (int mt = 0; mt < 4; mt++)
#pragma unroll
                for (int nt = 0; nt < 4; nt++)
                    mma_f16(F.acc[mt][nt], af[mt][0], af[mt][1], af[mt][2], af[mt][3],
                            bf[nt][0], bf[nt][1]);
        }
    }
    CP_WAIT0();
}

// ---------------- GEMM1: h = fp16(relu(g_xg @ W1t^T + b1[e])) ----------------
// bid.x = row*2 + n_lo (row-fastest, N-pairs co-resident), bid.y = n_hi
__global__ __launch_bounds__(256, 2) void gemm1_kernel(const float* __restrict__ b1) {
    extern __shared__ uint32_t sm[];
    uint32_t* As = sm;
    uint32_t* Bs = sm + NSTAGE * STAGE_W;
    int tid = threadIdx.x;
    int row0 = (blockIdx.x >> 1) * TM;
    if (row0 >= g_off[NEXP]) return;
    int n0 = (blockIdx.y * 2 + (blockIdx.x & 1)) * TN;
    int e = 0;
#pragma unroll
    for (int i = 1; i < NEXP; i++) e += (row0 >= g_off[i]) ? 1 : 0;

    const __half* Agm = g_xg + (size_t)row0 * DIMD;
    const __half* Bgm = g_w1t + (size_t)e * FF * DIMD + (size_t)n0 * DIMD;

    Frag F;
    gemm_mainloop(F, As, Bs, Agm, DIMD, Bgm, DIMD, DIMD / KT, tid);

    int lane = tid & 31, wid = tid >> 5;
    int warp_m = wid & 1, warp_n = wid >> 1;
    int gid = lane >> 2, tig = lane & 3;
    const float* bias = b1 + e * FF + n0;

#pragma unroll
    for (int nt = 0; nt < 4; nt++) {
        int gc = warp_n * 32 + nt * 8 + tig * 2;
        float bv0 = __ldg(bias + gc), bv1 = __ldg(bias + gc + 1);
#pragma unroll
        for (int mt = 0; mt < 4; mt++) {
            int gr0 = row0 + warp_m * 64 + mt * 16 + gid;
            __half2 v0 = __floats2half2_rn(fmaxf(F.acc[mt][nt][0] + bv0, 0.f),
                                           fmaxf(F.acc[mt][nt][1] + bv1, 0.f));
            __half2 v1 = __floats2half2_rn(fmaxf(F.acc[mt][nt][2] + bv0, 0.f),
                                           fmaxf(F.acc[mt][nt][3] + bv1, 0.f));
            *(__half2*)(g_h + (size_t)gr0 * FF + n0 + gc) = v0;
            *(__half2*)(g_h + (size_t)(gr0 + 8) * FF + n0 + gc) = v1;
        }
    }
}

// ---------------- GEMM2: y = h @ W2t^T  (bias+gate applied in combine) ----------------
__global__ __launch_bounds__(256, 2) void gemm2_kernel() {
    extern __shared__ uint32_t sm[];
    uint32_t* As = sm;
    uint32_t* Bs = sm + NSTAGE * STAGE_W;
    int tid = threadIdx.x;
    int row0 = (blockIdx.x >> 1) * TM;
    if (row0 >= g_off[NEXP]) return;
    int n0 = (blockIdx.y * 2 + (blockIdx.x & 1)) * TN;
    int e = 0;
#pragma unroll
    for (int i = 1; i < NEXP; i++) e += (row0 >= g_off[i]) ? 1 : 0;

    const __half* Agm = g_h + (size_t)row0 * FF;
    const __half* Bgm = g_w2t + (size_t)e * DIMD * FF + (size_t)n0 * FF;

    Frag F;
    gemm_mainloop(F, As, Bs, Agm, FF, Bgm, FF, FF / KT, tid);

    int lane = tid & 31, wid = tid >> 5;
    int warp_m = wid & 1, warp_n = wid >> 1;
    int gid = lane >> 2, tig = lane & 3;

#pragma unroll
    for (int nt = 0; nt < 4; nt++) {
        int gc = warp_n * 32 + nt * 8 + tig * 2;
#pragma unroll
        for (int mt = 0; mt < 4; mt++) {
            int gr0 = row0 + warp_m * 64 + mt * 16 + gid;
            float2 v0 = { F.acc[mt][nt][0], F.acc[mt][nt][1] };
            float2 v1 = { F.acc[mt][nt][2], F.acc[mt][nt][3] };
            *(float2*)(g_y + (size_t)gr0 * DIMD + n0 + gc) = v0;
            *(float2*)(g_y + (size_t)(gr0 + 8) * DIMD + n0 + gc) = v1;
        }
    }
}

// ---------------- combine: out[t] = sum_k g_k*(y[row_k] + b2[e_k]) ----------------
__global__ __launch_bounds__(256) void combine_kernel(const float* __restrict__ b2,
                                                      float* __restrict__ out) {
    int t = blockIdx.x;
    int d = threadIdx.x * 4;
    int r0 = g_tok_row[t * 2], r1 = g_tok_row[t * 2 + 1];
    int e0 = g_tok_e[t * 2],   e1 = g_tok_e[t * 2 + 1];
    float gg0 = g_tok_g[t * 2], gg1 = g_tok_g[t * 2 + 1];
    float4 y0 = *(const float4*)(g_y + (size_t)r0 * DIMD + d);
    float4 y1 = *(const float4*)(g_y + (size_t)r1 * DIMD + d);
    float4 bA = *(const float4*)(b2 + (size_t)e0 * DIMD + d);
    float4 bB = *(const float4*)(b2 + (size_t)e1 * DIMD + d);
    float4 o;
    o.x = gg0 * (y0.x + bA.x) + gg1 * (y1.x + bB.x);
    o.y = gg0 * (y0.y + bA.y) + gg1 * (y1.y + bB.y);
    o.z = gg0 * (y0.z + bA.z) + gg1 * (y1.z + bB.z);
    o.w = gg0 * (y0.w + bA.w) + gg1 * (y1.w + bB.w);
    *(float4*)(out + (size_t)t * DIMD + d) = o;
}

// ---------------- host launch ----------------
extern "C" void kernel_launch(void* const* d_in, const int* in_sizes, int n_in,
                              void* d_out, int out_size) {
    const float* x  = (const float*)d_in[0];
    const float* Wg = (const float*)d_in[1];
    const float* W1 = (const float*)d_in[2];
    const float* b1 = (const float*)d_in[3];
    const float* W2 = (const float*)d_in[4];
    const float* b2 = (const float*)d_in[5];
    float* out = (float*)d_out;

    cudaFuncSetAttribute(gemm1_kernel, cudaFuncAttributeMaxDynamicSharedMemorySize, SMEM_BYTES);
    cudaFuncSetAttribute(gemm2_kernel, cudaFuncAttributeMaxDynamicSharedMemorySize, SMEM_BYTES);

    init_kernel<<<R_CAP / 256, 256>>>();
    router_kernel<<<TOK / 8, 256>>>(x, Wg);
    scan_kernel<<<1, 32>>>();
    assign_kernel<<<TOK / 256, 256>>>();
    prep_x_kernel<<<(R_CAP * (DIMD / 4)) / 256, 256>>>(x);
    transpose_w1_kernel<<<dim3(FF / 64, DIMD / 64, NEXP), dim3(32, 8)>>>(W1);
    transpose_w2_kernel<<<dim3(DIMD / 64, FF / 64, NEXP), dim3(32, 8)>>>(W2);
    gemm1_kernel<<<dim3(ROW_TILES * 2, FF / (TN * 2)), 256, SMEM_BYTES>>>(b1);
    gemm2_kernel<<<dim3(ROW_TILES * 2, DIMD / (TN * 2)), 256, SMEM_BYTES>>>();
    combine_kernel<<<TOK, 256>>>(b2, out);
}